// round 8
// baseline (speedup 1.0000x reference)
#include <cuda_runtime.h>
#include <cuda_fp16.h>
#include <cstdint>

#define NN 50000
#define DD 256
#define EE 400000
#define LN_EPS 1e-5f

#define M_TOT (3 * NN)
#define NB ((M_TOT + 1023) / 1024)   // 147

// GEMM config (R5-proven): fp16 A via cp.async, fp16 B, 3 stages, BK=64
#define BM 128
#define BN 64
#define BK 64
#define STAGES 3
#define KTILES (DD / BK)          // 4
#define SA 36                      // uint32 row stride in smem (conflict-free)
#define A_STG (BM * SA)
#define B_STG (BN * SA)
#define GEMM_SMEM_BYTES ((STAGES * (A_STG + B_STG)) * 4)   // 82944

// ---------------- device scratch ----------------
__device__ __half d_Wh[DD * DD];              // ((W0+W1+W2)/3)^T fp16, [n][k]
__device__ __half d_feat16[(size_t)NN * DD];  // feat in fp16
__device__ __half d_h[(size_t)NN * DD];       // feat @ Wsum (fp16)
__device__ int    d_deg[M_TOT];               // self-cleaned by scan_p23
__device__ int    d_off[M_TOT + 1];
__device__ int    d_cur[M_TOT];
__device__ int    d_ss[3 * EE];
__device__ int    d_bsum[NB];

// ---------------- helpers ----------------
__device__ __forceinline__ void mma_f16(float (&d)[4], const uint32_t (&a)[4],
                                        const uint32_t (&b)[2]) {
    asm volatile(
        "mma.sync.aligned.m16n8k16.row.col.f32.f16.f16.f32 "
        "{%0,%1,%2,%3}, {%4,%5,%6,%7}, {%8,%9}, {%0,%1,%2,%3};\n"
        : "+f"(d[0]), "+f"(d[1]), "+f"(d[2]), "+f"(d[3])
        : "r"(a[0]), "r"(a[1]), "r"(a[2]), "r"(a[3]), "r"(b[0]), "r"(b[1]));
}

__device__ __forceinline__ void cp_async16(uint32_t dst_smem, const void* src, int src_bytes) {
    asm volatile("cp.async.cg.shared.global [%0], [%1], 16, %2;\n"
                 :: "r"(dst_smem), "l"(src), "r"(src_bytes));
}
__device__ __forceinline__ void cp_commit() { asm volatile("cp.async.commit_group;\n"); }
template <int N>
__device__ __forceinline__ void cp_wait() { asm volatile("cp.async.wait_group %0;\n" :: "n"(N)); }

__device__ __forceinline__ float warp_sum(float v) {
#pragma unroll
    for (int o = 16; o; o >>= 1) v += __shfl_xor_sync(0xFFFFFFFFu, v, o);
    return v;
}
__device__ __forceinline__ int warp_isum(int v) {
#pragma unroll
    for (int o = 16; o; o >>= 1) v += __shfl_xor_sync(0xFFFFFFFFu, v, o);
    return v;
}
__device__ __forceinline__ int warp_iscan(int x, int lane) {
#pragma unroll
    for (int ofs = 1; ofs < 32; ofs <<= 1) {
        int y = __shfl_up_sync(0xFFFFFFFFu, x, ofs);
        if (lane >= ofs) x += y;
    }
    return x;
}

// ---------------- fused prep: Wsum^T fp16 + feat -> fp16 ----------------
__global__ __launch_bounds__(256) void prep_conv_kernel(const float* __restrict__ feat,
                                                        const float* __restrict__ W0,
                                                        const float* __restrict__ W1,
                                                        const float* __restrict__ W2) {
    const int tid = blockIdx.x * blockDim.x + threadIdx.x;
    const int stride = gridDim.x * blockDim.x;

    // W part: one element each for the first DD*DD threads
    if (tid < DD * DD) {
        int n = tid >> 8, k = tid & 255;
        int src = k * DD + n;
        d_Wh[tid] = __float2half_rn((W0[src] + W1[src] + W2[src]) * (1.0f / 3.0f));
    }

    // feat convert: grid-stride over uint4 chunks (8 halves each)
    const int total = NN * DD / 8;
    const float4* in = reinterpret_cast<const float4*>(feat);
    uint4* out = reinterpret_cast<uint4*>(d_feat16);
    for (int i = tid; i < total; i += stride) {
        float4 a = in[2 * i];
        float4 b = in[2 * i + 1];
        __half2 h0 = __floats2half2_rn(a.x, a.y);
        __half2 h1 = __floats2half2_rn(a.z, a.w);
        __half2 h2 = __floats2half2_rn(b.x, b.y);
        __half2 h3 = __floats2half2_rn(b.z, b.w);
        uint4 u;
        u.x = *reinterpret_cast<uint32_t*>(&h0);
        u.y = *reinterpret_cast<uint32_t*>(&h1);
        u.z = *reinterpret_cast<uint32_t*>(&h2);
        u.w = *reinterpret_cast<uint32_t*>(&h3);
        out[i] = u;
    }
}

// ---------------- GEMM: h = feat16 @ Wh^T, 3-stage cp.async (R5-proven) ---
__global__ __launch_bounds__(256) void gemm_kernel() {
    extern __shared__ uint32_t smp[];
    uint32_t* As = smp;                      // [STAGES][BM*SA]
    uint32_t* Bs = smp + STAGES * A_STG;     // [STAGES][BN*SA]

    const int t    = threadIdx.x;
    const int lane = t & 31, wid = t >> 5;
    const int g    = lane >> 2, tig = lane & 3;
    const int wm   = wid & 3, wn = wid >> 2;

    const int rowBase = blockIdx.x * BM;
    const int colBase = blockIdx.y * BN;

    float acc[2][4][4];
#pragma unroll
    for (int mf = 0; mf < 2; mf++)
#pragma unroll
        for (int nf = 0; nf < 4; nf++)
#pragma unroll
            for (int k = 0; k < 4; k++) acc[mf][nf][k] = 0.0f;

    const int aRow = t >> 1, aHalf = t & 1;
    const int aGr  = rowBase + aRow;
    const int aValid = (aGr < NN) ? 16 : 0;
    const __half* aSrc = &d_feat16[(size_t)(aGr < NN ? aGr : NN - 1) * DD];
    const int bRow = t >> 2, bQ = t & 3;
    const __half* bSrc = &d_Wh[(colBase + bRow) * DD];

    const uint32_t asBase = (uint32_t)__cvta_generic_to_shared(As);
    const uint32_t bsBase = (uint32_t)__cvta_generic_to_shared(Bs);

    auto issue = [&](int stage, int kt) {
#pragma unroll
        for (int j = 0; j < 4; j++) {
            int chunk = aHalf * 4 + j;
            uint32_t dst = asBase + (stage * A_STG + aRow * SA + chunk * 4) * 4;
            cp_async16(dst, aSrc + kt + chunk * 8, aValid);
        }
#pragma unroll
        for (int j = 0; j < 2; j++) {
            int chunk = bQ * 2 + j;
            uint32_t dst = bsBase + (stage * B_STG + bRow * SA + chunk * 4) * 4;
            cp_async16(dst, bSrc + kt + chunk * 8, 16);
        }
    };

    issue(0, 0);
    cp_commit();
    issue(1, BK);
    cp_commit();

#pragma unroll
    for (int i = 0; i < KTILES; i++) {
        cp_wait<STAGES - 2>();
        __syncthreads();

        if (i + 2 < KTILES) issue((i + 2) % STAGES, (i + 2) * BK);
        cp_commit();

        const uint32_t* Ast = As + (i % STAGES) * A_STG;
        const uint32_t* Bst = Bs + (i % STAGES) * B_STG;

#pragma unroll
        for (int kk = 0; kk < 4; kk++) {
            uint32_t af[2][4], bf[4][2];
#pragma unroll
            for (int mf = 0; mf < 2; mf++) {
                int m0 = wm * 32 + mf * 16 + g;
                af[mf][0] = Ast[(m0)     * SA + kk * 8 + tig];
                af[mf][1] = Ast[(m0 + 8) * SA + kk * 8 + tig];
                af[mf][2] = Ast[(m0)     * SA + kk * 8 + tig + 4];
                af[mf][3] = Ast[(m0 + 8) * SA + kk * 8 + tig + 4];
            }
#pragma unroll
            for (int nf = 0; nf < 4; nf++) {
                int n0 = wn * 32 + nf * 8 + g;
                bf[nf][0] = Bst[n0 * SA + kk * 8 + tig];
                bf[nf][1] = Bst[n0 * SA + kk * 8 + tig + 4];
            }
#pragma unroll
            for (int mf = 0; mf < 2; mf++)
#pragma unroll
                for (int nf = 0; nf < 4; nf++) mma_f16(acc[mf][nf], af[mf], bf[nf]);
        }
        __syncthreads();
    }

    // epilogue -> fp16
#pragma unroll
    for (int mf = 0; mf < 2; mf++)
#pragma unroll
        for (int nf = 0; nf < 4; nf++) {
            int r0 = rowBase + wm * 32 + mf * 16 + g;
            int c  = colBase + wn * 32 + nf * 8 + tig * 2;
            if (r0 < NN)
                *reinterpret_cast<__half2*>(&d_h[(size_t)r0 * DD + c]) =
                    __floats2half2_rn(acc[mf][nf][0], acc[mf][nf][1]);
            int r1 = r0 + 8;
            if (r1 < NN)
                *reinterpret_cast<__half2*>(&d_h[(size_t)r1 * DD + c]) =
                    __floats2half2_rn(acc[mf][nf][2], acc[mf][nf][3]);
        }
}

// ---------------- degree histogram (deg pre-zeroed by previous run) -------
__global__ void hist_kernel(const int* __restrict__ dst0, const int* __restrict__ dst1,
                            const int* __restrict__ dst2) {
    int e = blockIdx.x * blockDim.x + threadIdx.x;
    int r = blockIdx.y;
    if (e >= EE) return;
    const int* dst = (r == 0) ? dst0 : (r == 1) ? dst1 : dst2;
    atomicAdd(&d_deg[r * NN + dst[e]], 1);
}

// ---------------- scan pass 1: block partial sums ----------------
__global__ __launch_bounds__(256) void scan_p1() {
    int b = blockIdx.x, t = threadIdx.x;
    int lane = t & 31, w = t >> 5;
    int base = b * 1024 + t * 4;
    int x = 0;
#pragma unroll
    for (int j = 0; j < 4; j++) {
        int i = base + j;
        if (i < M_TOT) x += d_deg[i];
    }
    x = warp_isum(x);
    __shared__ int ws[8];
    if (lane == 0) ws[w] = x;
    __syncthreads();
    if (t == 0) {
        int tot = 0;
#pragma unroll
        for (int j = 0; j < 8; j++) tot += ws[j];
        d_bsum[b] = tot;
    }
}

// ---------------- scan pass 2 (fused): offsets + deg self-clean ----------
__global__ __launch_bounds__(256) void scan_p23() {
    int b = blockIdx.x, t = threadIdx.x;
    int lane = t & 31, w = t >> 5;
    __shared__ int sb[NB];
    __shared__ int ws[8];

    int vb = (t < NB) ? d_bsum[t] : 0;
    int xb = warp_iscan(vb, lane);
    if (lane == 31) ws[w] = xb;
    __syncthreads();
    if (w == 0) {
        int y = (lane < 8) ? ws[lane] : 0;
        y = warp_iscan(y, lane);
        if (lane < 8) ws[lane] = y;
    }
    __syncthreads();
    int blkb = (w > 0) ? ws[w - 1] : 0;
    if (t < NB) sb[t] = xb + blkb;
    __syncthreads();
    int base_excl = (b > 0) ? sb[b - 1] : 0;
    __syncthreads();

    int base = b * 1024 + t * 4;
    int a[4];
#pragma unroll
    for (int j = 0; j < 4; j++) {
        int i = base + j;
        a[j] = (i < M_TOT) ? d_deg[i] : 0;
    }
    int tot = a[0] + a[1] + a[2] + a[3];
    int x = warp_iscan(tot, lane);
    if (lane == 31) ws[w] = x;
    __syncthreads();
    if (w == 0) {
        int y = (lane < 8) ? ws[lane] : 0;
        y = warp_iscan(y, lane);
        if (lane < 8) ws[lane] = y;
    }
    __syncthreads();
    int blk = (w > 0) ? ws[w - 1] : 0;
    int run = x - tot + blk + base_excl;
#pragma unroll
    for (int j = 0; j < 4; j++) {
        int i = base + j;
        if (i < M_TOT) {
            d_off[i] = run;
            d_cur[i] = run;
            d_deg[i] = 0;
        }
        run += a[j];
    }
    if (b == 0 && t == 0) d_off[M_TOT] = 3 * EE;
}

// ---------------- scatter into CSR ----------------
__global__ void scatter_kernel(const int* __restrict__ src0, const int* __restrict__ dst0,
                               const int* __restrict__ src1, const int* __restrict__ dst1,
                               const int* __restrict__ src2, const int* __restrict__ dst2) {
    int e = blockIdx.x * blockDim.x + threadIdx.x;
    int r = blockIdx.y;
    if (e >= EE) return;
    const int* src = (r == 0) ? src0 : (r == 1) ? src1 : src2;
    const int* dst = (r == 0) ? dst0 : (r == 1) ? dst1 : dst2;
    int dv = dst[e];
    int pos = atomicAdd(&d_cur[r * NN + dv], 1);
    d_ss[pos] = src[e];
}

// ---------------- gather + mean + relu + LN (warp/node, LDG.128, 4-way) ---
__device__ __forceinline__ void accum_row(float (&sm)[8], uint4 x) {
    float2 f0 = __half22float2(*reinterpret_cast<__half2*>(&x.x));
    float2 f1 = __half22float2(*reinterpret_cast<__half2*>(&x.y));
    float2 f2 = __half22float2(*reinterpret_cast<__half2*>(&x.z));
    float2 f3 = __half22float2(*reinterpret_cast<__half2*>(&x.w));
    sm[0] += f0.x; sm[1] += f0.y; sm[2] += f1.x; sm[3] += f1.y;
    sm[4] += f2.x; sm[5] += f2.y; sm[6] += f3.x; sm[7] += f3.y;
}

__global__ __launch_bounds__(256) void agg_ln_kernel(const float* __restrict__ gamma,
                                                     const float* __restrict__ beta,
                                                     float* __restrict__ out) {
    int v = (blockIdx.x * blockDim.x + threadIdx.x) >> 5;
    if (v >= NN) return;
    int lane = threadIdx.x & 31;
    const int co = lane * 8;

    float acc[8];
#pragma unroll
    for (int j = 0; j < 8; j++) acc[j] = 0.0f;

#pragma unroll
    for (int r = 0; r < 3; r++) {
        int s = d_off[r * NN + v];
        int e = d_off[r * NN + v + 1];
        float sm[8];
#pragma unroll
        for (int j = 0; j < 8; j++) sm[j] = 0.0f;

        int i = s;
        for (; i + 4 <= e; i += 4) {
            int u0 = d_ss[i], u1 = d_ss[i + 1], u2 = d_ss[i + 2], u3 = d_ss[i + 3];
            uint4 x0 = *reinterpret_cast<const uint4*>(&d_h[(size_t)u0 * DD + co]);
            uint4 x1 = *reinterpret_cast<const uint4*>(&d_h[(size_t)u1 * DD + co]);
            uint4 x2 = *reinterpret_cast<const uint4*>(&d_h[(size_t)u2 * DD + co]);
            uint4 x3 = *reinterpret_cast<const uint4*>(&d_h[(size_t)u3 * DD + co]);
            accum_row(sm, x0); accum_row(sm, x1); accum_row(sm, x2); accum_row(sm, x3);
        }
        for (; i < e; i++) {
            int u = d_ss[i];
            uint4 x = *reinterpret_cast<const uint4*>(&d_h[(size_t)u * DD + co]);
            accum_row(sm, x);
        }

        float inv = 1.0f / (float)max(e - s, 1);
#pragma unroll
        for (int j = 0; j < 8; j++) acc[j] += sm[j] * inv;
    }

#pragma unroll
    for (int j = 0; j < 8; j++) acc[j] = fmaxf(acc[j] * (1.0f / 3.0f), 0.0f);

    float loc = 0.0f;
#pragma unroll
    for (int j = 0; j < 8; j++) loc += acc[j];
    float mu = warp_sum(loc) * (1.0f / 256.0f);

    float vs = 0.0f;
#pragma unroll
    for (int j = 0; j < 8; j++) {
        float dlt = acc[j] - mu;
        vs += dlt * dlt;
    }
    float var = warp_sum(vs) * (1.0f / 256.0f);
    float rstd = rsqrtf(var + LN_EPS);

    const float4* g4 = reinterpret_cast<const float4*>(gamma);
    const float4* b4 = reinterpret_cast<const float4*>(beta);
    float4 ga = g4[lane * 2], gb = g4[lane * 2 + 1];
    float4 ba = b4[lane * 2], bb = b4[lane * 2 + 1];

    float4 o0, o1;
    o0.x = (acc[0] - mu) * rstd * ga.x + ba.x;
    o0.y = (acc[1] - mu) * rstd * ga.y + ba.y;
    o0.z = (acc[2] - mu) * rstd * ga.z + ba.z;
    o0.w = (acc[3] - mu) * rstd * ga.w + ba.w;
    o1.x = (acc[4] - mu) * rstd * gb.x + bb.x;
    o1.y = (acc[5] - mu) * rstd * gb.y + bb.y;
    o1.z = (acc[6] - mu) * rstd * gb.z + bb.z;
    o1.w = (acc[7] - mu) * rstd * gb.w + bb.w;

    float4* out4 = reinterpret_cast<float4*>(&out[(size_t)v * DD]);
    out4[lane * 2] = o0;
    out4[lane * 2 + 1] = o1;
}

// ---------------- launch ----------------
extern "C" void kernel_launch(void* const* d_in, const int* in_sizes, int n_in,
                              void* d_out, int out_size) {
    const float* feat  = (const float*)d_in[0];
    const float* W0    = (const float*)d_in[1];
    const float* W1    = (const float*)d_in[2];
    const float* W2    = (const float*)d_in[3];
    const float* gamma = (const float*)d_in[7];
    const float* beta  = (const float*)d_in[8];
    const int* src0 = (const int*)d_in[9];
    const int* dst0 = (const int*)d_in[10];
    const int* src1 = (const int*)d_in[11];
    const int* dst1 = (const int*)d_in[12];
    const int* src2 = (const int*)d_in[13];
    const int* dst2 = (const int*)d_in[14];
    float* out = (float*)d_out;

    static cudaStream_t s_side = nullptr;
    static cudaEvent_t ev_fork = nullptr, ev_join = nullptr;
    if (s_side == nullptr) {
        cudaStreamCreateWithFlags(&s_side, cudaStreamNonBlocking);
        cudaEventCreateWithFlags(&ev_fork, cudaEventDisableTiming);
        cudaEventCreateWithFlags(&ev_join, cudaEventDisableTiming);
        cudaFuncSetAttribute(gemm_kernel, cudaFuncAttributeMaxDynamicSharedMemorySize,
                             GEMM_SMEM_BYTES);
    }

    // submission idx 0: fused prep (Wsum fp16 + feat fp16), main stream
    prep_conv_kernel<<<592, 256>>>(feat, W0, W1, W2);

    // fork to side stream
    cudaEventRecord(ev_fork, 0);
    cudaStreamWaitEvent(s_side, ev_fork, 0);

    dim3 egrid((EE + 255) / 256, 3);
    hist_kernel<<<egrid, 256, 0, s_side>>>(dst0, dst1, dst2);   // idx 1
    scan_p1<<<NB, 256, 0, s_side>>>();                          // idx 2

    // idx 3 (profiled slot): GEMM on main stream — depends only on prep_conv
    dim3 ggrid((NN + BM - 1) / BM, DD / BN);
    gemm_kernel<<<ggrid, 256, GEMM_SMEM_BYTES, 0>>>();          // idx 3

    scan_p23<<<NB, 256, 0, s_side>>>();                         // idx 4
    scatter_kernel<<<egrid, 256, 0, s_side>>>(src0, dst0, src1, dst1, src2, dst2); // idx 5
    cudaEventRecord(ev_join, s_side);

    // join + final fused aggregate/LN
    cudaStreamWaitEvent(0, ev_join, 0);
    agg_ln_kernel<<<(NN * 32 + 255) / 256, 256>>>(gamma, beta, out);  // idx 6
}

// round 9
// speedup vs baseline: 1.4382x; 1.4382x over previous
#include <cuda_runtime.h>
#include <cuda_fp16.h>
#include <cstdint>

#define NN 50000
#define DD 256
#define EE 400000
#define LN_EPS 1e-5f

#define M_TOT (3 * NN)
#define NB ((M_TOT + 1023) / 1024)   // 147

// GEMM config: fp16, BK=32, 3-stage cp.async, LDSM A fragments, 4 CTA/SM
#define BM 128
#define BN 64
#define BK 32
#define STAGES 3
#define KTILES (DD / BK)             // 8
#define SA 20                        // uint32 row stride (16 data + 4 pad) = 80B
#define A_STG (BM * SA)              // 2560 words
#define B_STG (BN * SA)              // 1280 words
#define GEMM_SMEM_BYTES ((STAGES * (A_STG + B_STG)) * 4)   // 46080

// ---------------- device scratch ----------------
__device__ __half d_Wh[DD * DD];              // ((W0+W1+W2)/3)^T fp16, [n][k]
__device__ __half d_feat16[(size_t)NN * DD];  // feat in fp16
__device__ __half d_h[(size_t)NN * DD];       // feat @ Wsum (fp16)
__device__ int    d_deg[M_TOT];               // self-cleaned by scan_p23
__device__ int    d_off[M_TOT + 1];
__device__ int    d_cur[M_TOT];
__device__ int    d_ss[3 * EE];
__device__ int    d_bsum[NB];

// ---------------- helpers ----------------
__device__ __forceinline__ void mma_f16(float (&d)[4], const uint32_t (&a)[4],
                                        const uint32_t (&b)[2]) {
    asm volatile(
        "mma.sync.aligned.m16n8k16.row.col.f32.f16.f16.f32 "
        "{%0,%1,%2,%3}, {%4,%5,%6,%7}, {%8,%9}, {%0,%1,%2,%3};\n"
        : "+f"(d[0]), "+f"(d[1]), "+f"(d[2]), "+f"(d[3])
        : "r"(a[0]), "r"(a[1]), "r"(a[2]), "r"(a[3]), "r"(b[0]), "r"(b[1]));
}

__device__ __forceinline__ void ldsm_x4(uint32_t (&r)[4], uint32_t saddr) {
    asm volatile("ldmatrix.sync.aligned.m8n8.x4.shared.b16 {%0,%1,%2,%3}, [%4];\n"
                 : "=r"(r[0]), "=r"(r[1]), "=r"(r[2]), "=r"(r[3]) : "r"(saddr));
}

__device__ __forceinline__ void cp_async16(uint32_t dst_smem, const void* src, int src_bytes) {
    asm volatile("cp.async.cg.shared.global [%0], [%1], 16, %2;\n"
                 :: "r"(dst_smem), "l"(src), "r"(src_bytes));
}
__device__ __forceinline__ void cp_commit() { asm volatile("cp.async.commit_group;\n"); }
template <int N>
__device__ __forceinline__ void cp_wait() { asm volatile("cp.async.wait_group %0;\n" :: "n"(N)); }

__device__ __forceinline__ float warp_sum(float v) {
#pragma unroll
    for (int o = 16; o; o >>= 1) v += __shfl_xor_sync(0xFFFFFFFFu, v, o);
    return v;
}
__device__ __forceinline__ int warp_isum(int v) {
#pragma unroll
    for (int o = 16; o; o >>= 1) v += __shfl_xor_sync(0xFFFFFFFFu, v, o);
    return v;
}
__device__ __forceinline__ int warp_iscan(int x, int lane) {
#pragma unroll
    for (int ofs = 1; ofs < 32; ofs <<= 1) {
        int y = __shfl_up_sync(0xFFFFFFFFu, x, ofs);
        if (lane >= ofs) x += y;
    }
    return x;
}

// ---------------- fused prep: Wsum^T fp16 + feat -> fp16 ----------------
__global__ __launch_bounds__(256) void prep_conv_kernel(const float* __restrict__ feat,
                                                        const float* __restrict__ W0,
                                                        const float* __restrict__ W1,
                                                        const float* __restrict__ W2) {
    const int tid = blockIdx.x * blockDim.x + threadIdx.x;
    const int stride = gridDim.x * blockDim.x;

    if (tid < DD * DD) {
        int n = tid >> 8, k = tid & 255;
        int src = k * DD + n;
        d_Wh[tid] = __float2half_rn((W0[src] + W1[src] + W2[src]) * (1.0f / 3.0f));
    }

    const int total = NN * DD / 8;
    const float4* in = reinterpret_cast<const float4*>(feat);
    uint4* out = reinterpret_cast<uint4*>(d_feat16);
    for (int i = tid; i < total; i += stride) {
        float4 a = in[2 * i];
        float4 b = in[2 * i + 1];
        __half2 h0 = __floats2half2_rn(a.x, a.y);
        __half2 h1 = __floats2half2_rn(a.z, a.w);
        __half2 h2 = __floats2half2_rn(b.x, b.y);
        __half2 h3 = __floats2half2_rn(b.z, b.w);
        uint4 u;
        u.x = *reinterpret_cast<uint32_t*>(&h0);
        u.y = *reinterpret_cast<uint32_t*>(&h1);
        u.z = *reinterpret_cast<uint32_t*>(&h2);
        u.w = *reinterpret_cast<uint32_t*>(&h3);
        out[i] = u;
    }
}

// ---------------- GEMM: h = feat16 @ Wh^T ----------------
__global__ __launch_bounds__(256, 4) void gemm_kernel() {
    extern __shared__ uint32_t smp[];
    uint32_t* As = smp;                      // [STAGES][BM*SA]
    uint32_t* Bs = smp + STAGES * A_STG;     // [STAGES][BN*SA]

    const int t    = threadIdx.x;
    const int lane = t & 31, wid = t >> 5;
    const int g    = lane >> 2, tig = lane & 3;
    const int wm   = wid & 3, wn = wid >> 2;

    const int rowBase = blockIdx.x * BM;
    const int colBase = blockIdx.y * BN;

    float acc[2][4][4];
#pragma unroll
    for (int mf = 0; mf < 2; mf++)
#pragma unroll
        for (int nf = 0; nf < 4; nf++)
#pragma unroll
            for (int k = 0; k < 4; k++) acc[mf][nf][k] = 0.0f;

    // A loader: 2 threads/row, 2x 16B chunks each (row = 32 halves = 4 chunks)
    const int aRow = t >> 1, aHalf = t & 1;
    const int aGr  = rowBase + aRow;
    const int aValid = (aGr < NN) ? 16 : 0;
    const __half* aSrc = &d_feat16[(size_t)(aGr < NN ? aGr : NN - 1) * DD];
    // B loader: 4 threads/row, 1x 16B chunk each
    const int bRow = t >> 2, bQ = t & 3;
    const __half* bSrc = &d_Wh[(colBase + bRow) * DD];

    const uint32_t asBase = (uint32_t)__cvta_generic_to_shared(As);
    const uint32_t bsBase = (uint32_t)__cvta_generic_to_shared(Bs);

    auto issue = [&](int stage, int kt) {
#pragma unroll
        for (int j = 0; j < 2; j++) {
            int chunk = aHalf * 2 + j;
            uint32_t dst = asBase + (stage * A_STG + aRow * SA + chunk * 4) * 4;
            cp_async16(dst, aSrc + kt + chunk * 8, aValid);
        }
        {
            uint32_t dst = bsBase + (stage * B_STG + bRow * SA + bQ * 4) * 4;
            cp_async16(dst, bSrc + kt + bQ * 8, 16);
        }
    };

    issue(0, 0); cp_commit();
    issue(1, BK); cp_commit();

    // LDSM addressing for A (per mf): row = m0 + (lane&15), col = kk*16 + (lane>>4)*8
    const int lRow = lane & 15, lHi = lane >> 4;

#pragma unroll
    for (int i = 0; i < KTILES; i++) {
        cp_wait<STAGES - 2>();
        __syncthreads();

        if (i + 2 < KTILES) issue((i + 2) % STAGES, (i + 2) * BK);
        cp_commit();

        const int so = (i % STAGES) * A_STG;
        const uint32_t* Bst = Bs + (i % STAGES) * B_STG;

#pragma unroll
        for (int kk = 0; kk < 2; kk++) {
            uint32_t af[2][4], bf[4][2];
#pragma unroll
            for (int mf = 0; mf < 2; mf++) {
                int m0 = wm * 32 + mf * 16;
                uint32_t saddr = asBase + (so + (m0 + lRow) * SA) * 4 +
                                 (kk * 16 + lHi * 8) * 2;
                ldsm_x4(af[mf], saddr);
            }
#pragma unroll
            for (int nf = 0; nf < 4; nf++) {
                int n0 = wn * 32 + nf * 8 + g;
                bf[nf][0] = Bst[n0 * SA + kk * 8 + tig];
                bf[nf][1] = Bst[n0 * SA + kk * 8 + tig + 4];
            }
#pragma unroll
            for (int mf = 0; mf < 2; mf++)
#pragma unroll
                for (int nf = 0; nf < 4; nf++) mma_f16(acc[mf][nf], af[mf], bf[nf]);
        }
        __syncthreads();
    }

    // epilogue -> fp16
#pragma unroll
    for (int mf = 0; mf < 2; mf++)
#pragma unroll
        for (int nf = 0; nf < 4; nf++) {
            int r0 = rowBase + wm * 32 + mf * 16 + g;
            int c  = colBase + wn * 32 + nf * 8 + tig * 2;
            if (r0 < NN)
                *reinterpret_cast<__half2*>(&d_h[(size_t)r0 * DD + c]) =
                    __floats2half2_rn(acc[mf][nf][0], acc[mf][nf][1]);
            int r1 = r0 + 8;
            if (r1 < NN)
                *reinterpret_cast<__half2*>(&d_h[(size_t)r1 * DD + c]) =
                    __floats2half2_rn(acc[mf][nf][2], acc[mf][nf][3]);
        }
}

// ---------------- degree histogram (deg pre-zeroed by previous run) -------
__global__ void hist_kernel(const int* __restrict__ dst0, const int* __restrict__ dst1,
                            const int* __restrict__ dst2) {
    int e = blockIdx.x * blockDim.x + threadIdx.x;
    int r = blockIdx.y;
    if (e >= EE) return;
    const int* dst = (r == 0) ? dst0 : (r == 1) ? dst1 : dst2;
    atomicAdd(&d_deg[r * NN + dst[e]], 1);
}

// ---------------- scan pass 1: block partial sums ----------------
__global__ __launch_bounds__(256) void scan_p1() {
    int b = blockIdx.x, t = threadIdx.x;
    int lane = t & 31, w = t >> 5;
    int base = b * 1024 + t * 4;
    int x = 0;
#pragma unroll
    for (int j = 0; j < 4; j++) {
        int i = base + j;
        if (i < M_TOT) x += d_deg[i];
    }
    x = warp_isum(x);
    __shared__ int ws[8];
    if (lane == 0) ws[w] = x;
    __syncthreads();
    if (t == 0) {
        int tot = 0;
#pragma unroll
        for (int j = 0; j < 8; j++) tot += ws[j];
        d_bsum[b] = tot;
    }
}

// ---------------- scan pass 2 (fused): offsets + deg self-clean ----------
__global__ __launch_bounds__(256) void scan_p23() {
    int b = blockIdx.x, t = threadIdx.x;
    int lane = t & 31, w = t >> 5;
    __shared__ int sb[NB];
    __shared__ int ws[8];

    int vb = (t < NB) ? d_bsum[t] : 0;
    int xb = warp_iscan(vb, lane);
    if (lane == 31) ws[w] = xb;
    __syncthreads();
    if (w == 0) {
        int y = (lane < 8) ? ws[lane] : 0;
        y = warp_iscan(y, lane);
        if (lane < 8) ws[lane] = y;
    }
    __syncthreads();
    int blkb = (w > 0) ? ws[w - 1] : 0;
    if (t < NB) sb[t] = xb + blkb;
    __syncthreads();
    int base_excl = (b > 0) ? sb[b - 1] : 0;
    __syncthreads();

    int base = b * 1024 + t * 4;
    int a[4];
#pragma unroll
    for (int j = 0; j < 4; j++) {
        int i = base + j;
        a[j] = (i < M_TOT) ? d_deg[i] : 0;
    }
    int tot = a[0] + a[1] + a[2] + a[3];
    int x = warp_iscan(tot, lane);
    if (lane == 31) ws[w] = x;
    __syncthreads();
    if (w == 0) {
        int y = (lane < 8) ? ws[lane] : 0;
        y = warp_iscan(y, lane);
        if (lane < 8) ws[lane] = y;
    }
    __syncthreads();
    int blk = (w > 0) ? ws[w - 1] : 0;
    int run = x - tot + blk + base_excl;
#pragma unroll
    for (int j = 0; j < 4; j++) {
        int i = base + j;
        if (i < M_TOT) {
            d_off[i] = run;
            d_cur[i] = run;
            d_deg[i] = 0;
        }
        run += a[j];
    }
    if (b == 0 && t == 0) d_off[M_TOT] = 3 * EE;
}

// ---------------- scatter into CSR ----------------
__global__ void scatter_kernel(const int* __restrict__ src0, const int* __restrict__ dst0,
                               const int* __restrict__ src1, const int* __restrict__ dst1,
                               const int* __restrict__ src2, const int* __restrict__ dst2) {
    int e = blockIdx.x * blockDim.x + threadIdx.x;
    int r = blockIdx.y;
    if (e >= EE) return;
    const int* src = (r == 0) ? src0 : (r == 1) ? src1 : src2;
    const int* dst = (r == 0) ? dst0 : (r == 1) ? dst1 : dst2;
    int dv = dst[e];
    int pos = atomicAdd(&d_cur[r * NN + dv], 1);
    d_ss[pos] = src[e];
}

// ---------------- gather + mean + relu + LN (warp/node, LDG.128, 4-way) ---
__device__ __forceinline__ void accum_row(float (&sm)[8], uint4 x) {
    float2 f0 = __half22float2(*reinterpret_cast<__half2*>(&x.x));
    float2 f1 = __half22float2(*reinterpret_cast<__half2*>(&x.y));
    float2 f2 = __half22float2(*reinterpret_cast<__half2*>(&x.z));
    float2 f3 = __half22float2(*reinterpret_cast<__half2*>(&x.w));
    sm[0] += f0.x; sm[1] += f0.y; sm[2] += f1.x; sm[3] += f1.y;
    sm[4] += f2.x; sm[5] += f2.y; sm[6] += f3.x; sm[7] += f3.y;
}

__global__ __launch_bounds__(256) void agg_ln_kernel(const float* __restrict__ gamma,
                                                     const float* __restrict__ beta,
                                                     float* __restrict__ out) {
    int v = (blockIdx.x * blockDim.x + threadIdx.x) >> 5;
    if (v >= NN) return;
    int lane = threadIdx.x & 31;
    const int co = lane * 8;

    float acc[8];
#pragma unroll
    for (int j = 0; j < 8; j++) acc[j] = 0.0f;

#pragma unroll
    for (int r = 0; r < 3; r++) {
        int s = d_off[r * NN + v];
        int e = d_off[r * NN + v + 1];
        float sm[8];
#pragma unroll
        for (int j = 0; j < 8; j++) sm[j] = 0.0f;

        int i = s;
        for (; i + 4 <= e; i += 4) {
            int u0 = d_ss[i], u1 = d_ss[i + 1], u2 = d_ss[i + 2], u3 = d_ss[i + 3];
            uint4 x0 = *reinterpret_cast<const uint4*>(&d_h[(size_t)u0 * DD + co]);
            uint4 x1 = *reinterpret_cast<const uint4*>(&d_h[(size_t)u1 * DD + co]);
            uint4 x2 = *reinterpret_cast<const uint4*>(&d_h[(size_t)u2 * DD + co]);
            uint4 x3 = *reinterpret_cast<const uint4*>(&d_h[(size_t)u3 * DD + co]);
            accum_row(sm, x0); accum_row(sm, x1); accum_row(sm, x2); accum_row(sm, x3);
        }
        for (; i < e; i++) {
            int u = d_ss[i];
            uint4 x = *reinterpret_cast<const uint4*>(&d_h[(size_t)u * DD + co]);
            accum_row(sm, x);
        }

        float inv = 1.0f / (float)max(e - s, 1);
#pragma unroll
        for (int j = 0; j < 8; j++) acc[j] += sm[j] * inv;
    }

#pragma unroll
    for (int j = 0; j < 8; j++) acc[j] = fmaxf(acc[j] * (1.0f / 3.0f), 0.0f);

    float loc = 0.0f;
#pragma unroll
    for (int j = 0; j < 8; j++) loc += acc[j];
    float mu = warp_sum(loc) * (1.0f / 256.0f);

    float vs = 0.0f;
#pragma unroll
    for (int j = 0; j < 8; j++) {
        float dlt = acc[j] - mu;
        vs += dlt * dlt;
    }
    float var = warp_sum(vs) * (1.0f / 256.0f);
    float rstd = rsqrtf(var + LN_EPS);

    const float4* g4 = reinterpret_cast<const float4*>(gamma);
    const float4* b4 = reinterpret_cast<const float4*>(beta);
    float4 ga = g4[lane * 2], gb = g4[lane * 2 + 1];
    float4 ba = b4[lane * 2], bb = b4[lane * 2 + 1];

    float4 o0, o1;
    o0.x = (acc[0] - mu) * rstd * ga.x + ba.x;
    o0.y = (acc[1] - mu) * rstd * ga.y + ba.y;
    o0.z = (acc[2] - mu) * rstd * ga.z + ba.z;
    o0.w = (acc[3] - mu) * rstd * ga.w + ba.w;
    o1.x = (acc[4] - mu) * rstd * gb.x + bb.x;
    o1.y = (acc[5] - mu) * rstd * gb.y + bb.y;
    o1.z = (acc[6] - mu) * rstd * gb.z + bb.z;
    o1.w = (acc[7] - mu) * rstd * gb.w + bb.w;

    float4* out4 = reinterpret_cast<float4*>(&out[(size_t)v * DD]);
    out4[lane * 2] = o0;
    out4[lane * 2 + 1] = o1;
}

// ---------------- launch ----------------
extern "C" void kernel_launch(void* const* d_in, const int* in_sizes, int n_in,
                              void* d_out, int out_size) {
    const float* feat  = (const float*)d_in[0];
    const float* W0    = (const float*)d_in[1];
    const float* W1    = (const float*)d_in[2];
    const float* W2    = (const float*)d_in[3];
    const float* gamma = (const float*)d_in[7];
    const float* beta  = (const float*)d_in[8];
    const int* src0 = (const int*)d_in[9];
    const int* dst0 = (const int*)d_in[10];
    const int* src1 = (const int*)d_in[11];
    const int* dst1 = (const int*)d_in[12];
    const int* src2 = (const int*)d_in[13];
    const int* dst2 = (const int*)d_in[14];
    float* out = (float*)d_out;

    static cudaStream_t s_side = nullptr;
    static cudaEvent_t ev_fork = nullptr, ev_join = nullptr;
    if (s_side == nullptr) {
        cudaStreamCreateWithFlags(&s_side, cudaStreamNonBlocking);
        cudaEventCreateWithFlags(&ev_fork, cudaEventDisableTiming);
        cudaEventCreateWithFlags(&ev_join, cudaEventDisableTiming);
        cudaFuncSetAttribute(gemm_kernel, cudaFuncAttributeMaxDynamicSharedMemorySize,
                             GEMM_SMEM_BYTES);
    }

    // fork FIRST: side chain has no dependence on prep
    cudaEventRecord(ev_fork, 0);
    cudaStreamWaitEvent(s_side, ev_fork, 0);

    // main: fused prep (Wsum + feat->fp16)                 [kernel idx 0]
    prep_conv_kernel<<<592, 256>>>(feat, W0, W1, W2);

    dim3 egrid((EE + 255) / 256, 3);
    hist_kernel<<<egrid, 256, 0, s_side>>>(dst0, dst1, dst2);   // idx 1
    scan_p1<<<NB, 256, 0, s_side>>>();                          // idx 2

    // main: GEMM                                            [idx 3 - profiled]
    dim3 ggrid((NN + BM - 1) / BM, DD / BN);
    gemm_kernel<<<ggrid, 256, GEMM_SMEM_BYTES, 0>>>();

    scan_p23<<<NB, 256, 0, s_side>>>();                         // idx 4
    scatter_kernel<<<egrid, 256, 0, s_side>>>(src0, dst0, src1, dst1, src2, dst2); // idx 5
    cudaEventRecord(ev_join, s_side);

    cudaStreamWaitEvent(0, ev_join, 0);
    agg_ln_kernel<<<(NN * 32 + 255) / 256, 256>>>(gamma, beta, out);  // idx 6
}

// round 11
// speedup vs baseline: 1.4843x; 1.0320x over previous
#include <cuda_runtime.h>
#include <cuda_fp16.h>
#include <cstdint>

#define NN 50000
#define DD 256
#define EE 400000
#define LN_EPS 1e-5f

#define M_TOT (3 * NN)
#define NB ((M_TOT + 1023) / 1024)   // 147

// GEMM config: fp16, BK=32, 3-stage cp.async, LDSM A+B fragments, 4 CTA/SM
#define BM 128
#define BN 64
#define BK 32
#define STAGES 3
#define KTILES (DD / BK)             // 8
#define SA 20                        // uint32 row stride (16 data + 4 pad) = 80B
#define A_STG (BM * SA)              // 2560 words
#define B_STG (BN * SA)              // 1280 words
#define GEMM_SMEM_BYTES ((STAGES * (A_STG + B_STG)) * 4)   // 46080

// ---------------- device scratch ----------------
__device__ __half d_Wh[DD * DD];              // ((W0+W1+W2)/3)^T fp16, [n][k]
__device__ __half d_feat16[(size_t)NN * DD];  // feat in fp16
__device__ __half d_h[(size_t)NN * DD];       // feat @ Wsum (fp16)
__device__ int    d_deg[M_TOT];               // self-cleaned by scan_p23
__device__ int    d_off[M_TOT + 1];
__device__ int    d_cur[M_TOT];
__device__ int    d_ss[3 * EE];
__device__ int    d_bsum[NB];

// ---------------- helpers ----------------
__device__ __forceinline__ void mma_f16(float (&d)[4], const uint32_t (&a)[4],
                                        const uint32_t (&b)[2]) {
    asm volatile(
        "mma.sync.aligned.m16n8k16.row.col.f32.f16.f16.f32 "
        "{%0,%1,%2,%3}, {%4,%5,%6,%7}, {%8,%9}, {%0,%1,%2,%3};\n"
        : "+f"(d[0]), "+f"(d[1]), "+f"(d[2]), "+f"(d[3])
        : "r"(a[0]), "r"(a[1]), "r"(a[2]), "r"(a[3]), "r"(b[0]), "r"(b[1]));
}

__device__ __forceinline__ void ldsm_x4(uint32_t (&r)[4], uint32_t saddr) {
    asm volatile("ldmatrix.sync.aligned.m8n8.x4.shared.b16 {%0,%1,%2,%3}, [%4];\n"
                 : "=r"(r[0]), "=r"(r[1]), "=r"(r[2]), "=r"(r[3]) : "r"(saddr));
}

__device__ __forceinline__ void cp_async16(uint32_t dst_smem, const void* src, int src_bytes) {
    asm volatile("cp.async.cg.shared.global [%0], [%1], 16, %2;\n"
                 :: "r"(dst_smem), "l"(src), "r"(src_bytes));
}
__device__ __forceinline__ void cp_commit() { asm volatile("cp.async.commit_group;\n"); }
template <int N>
__device__ __forceinline__ void cp_wait() { asm volatile("cp.async.wait_group %0;\n" :: "n"(N)); }

__device__ __forceinline__ float warp_sum(float v) {
#pragma unroll
    for (int o = 16; o; o >>= 1) v += __shfl_xor_sync(0xFFFFFFFFu, v, o);
    return v;
}
__device__ __forceinline__ int warp_isum(int v) {
#pragma unroll
    for (int o = 16; o; o >>= 1) v += __shfl_xor_sync(0xFFFFFFFFu, v, o);
    return v;
}
__device__ __forceinline__ int warp_iscan(int x, int lane) {
#pragma unroll
    for (int ofs = 1; ofs < 32; ofs <<= 1) {
        int y = __shfl_up_sync(0xFFFFFFFFu, x, ofs);
        if (lane >= ofs) x += y;
    }
    return x;
}

// ---------------- fused prep: Wsum^T fp16 + feat -> fp16 ----------------
__global__ __launch_bounds__(256) void prep_conv_kernel(const float* __restrict__ feat,
                                                        const float* __restrict__ W0,
                                                        const float* __restrict__ W1,
                                                        const float* __restrict__ W2) {
    const int tid = blockIdx.x * blockDim.x + threadIdx.x;
    const int stride = gridDim.x * blockDim.x;

    if (tid < DD * DD) {
        int n = tid >> 8, k = tid & 255;
        int src = k * DD + n;
        d_Wh[tid] = __float2half_rn((W0[src] + W1[src] + W2[src]) * (1.0f / 3.0f));
    }

    const int total = NN * DD / 8;
    const float4* in = reinterpret_cast<const float4*>(feat);
    uint4* out = reinterpret_cast<uint4*>(d_feat16);
    for (int i = tid; i < total; i += stride) {
        float4 a = in[2 * i];
        float4 b = in[2 * i + 1];
        __half2 h0 = __floats2half2_rn(a.x, a.y);
        __half2 h1 = __floats2half2_rn(a.z, a.w);
        __half2 h2 = __floats2half2_rn(b.x, b.y);
        __half2 h3 = __floats2half2_rn(b.z, b.w);
        uint4 u;
        u.x = *reinterpret_cast<uint32_t*>(&h0);
        u.y = *reinterpret_cast<uint32_t*>(&h1);
        u.z = *reinterpret_cast<uint32_t*>(&h2);
        u.w = *reinterpret_cast<uint32_t*>(&h3);
        out[i] = u;
    }
}

// ---------------- GEMM: h = feat16 @ Wh^T ----------------
__global__ __launch_bounds__(256, 4) void gemm_kernel() {
    extern __shared__ uint32_t smp[];
    uint32_t* As = smp;                      // [STAGES][BM*SA]
    uint32_t* Bs = smp + STAGES * A_STG;     // [STAGES][BN*SA]

    const int t    = threadIdx.x;
    const int lane = t & 31, wid = t >> 5;
    const int g    = lane >> 2, tig = lane & 3;
    const int wm   = wid & 3, wn = wid >> 2;

    const int rowBase = blockIdx.x * BM;
    const int colBase = blockIdx.y * BN;

    float acc[2][4][4];
#pragma unroll
    for (int mf = 0; mf < 2; mf++)
#pragma unroll
        for (int nf = 0; nf < 4; nf++)
#pragma unroll
            for (int k = 0; k < 4; k++) acc[mf][nf][k] = 0.0f;

    // A loader: 2 threads/row, 2x 16B chunks each
    const int aRow = t >> 1, aHalf = t & 1;
    const int aGr  = rowBase + aRow;
    const int aValid = (aGr < NN) ? 16 : 0;
    const __half* aSrc = &d_feat16[(size_t)(aGr < NN ? aGr : NN - 1) * DD];
    // B loader: 4 threads/row, 1x 16B chunk each
    const int bRow = t >> 2, bQ = t & 3;
    const __half* bSrc = &d_Wh[(colBase + bRow) * DD];

    const uint32_t asBase = (uint32_t)__cvta_generic_to_shared(As);
    const uint32_t bsBase = (uint32_t)__cvta_generic_to_shared(Bs);

    auto issue = [&](int stage, int kt) {
#pragma unroll
        for (int j = 0; j < 2; j++) {
            int chunk = aHalf * 2 + j;
            uint32_t dst = asBase + (stage * A_STG + aRow * SA + chunk * 4) * 4;
            cp_async16(dst, aSrc + kt + chunk * 8, aValid);
        }
        {
            uint32_t dst = bsBase + (stage * B_STG + bRow * SA + bQ * 4) * 4;
            cp_async16(dst, bSrc + kt + bQ * 8, 16);
        }
    };

    issue(0, 0); cp_commit();
    issue(1, BK); cp_commit();

    // A LDSM addressing: row = m0 + (lane&15), col-bytes = kk*32 + (lane>>4)*16
    const int lRow = lane & 15, lHi = lane >> 4;
    // B LDSM addressing: mat = lane>>3 (0..3), i = lane&7
    //   nf = nb + (mat>>1), half = mat&1, row = wn*32 + nf*8 + i
    const int bMat = lane >> 3, bI = lane & 7;
    const int bNfOff = (bMat >> 1) * 8 + bI;   // row offset within nb-group
    const int bHalf = bMat & 1;

#pragma unroll
    for (int i = 0; i < KTILES; i++) {
        cp_wait<STAGES - 2>();
        __syncthreads();

        if (i + 2 < KTILES) issue((i + 2) % STAGES, (i + 2) * BK);
        cp_commit();

        const int so = (i % STAGES) * A_STG;
        const int sob = (i % STAGES) * B_STG;

#pragma unroll
        for (int kk = 0; kk < 2; kk++) {
            uint32_t af[2][4], bfr[2][4];
#pragma unroll
            for (int mf = 0; mf < 2; mf++) {
                int m0 = wm * 32 + mf * 16;
                uint32_t saddr = asBase + (so + (m0 + lRow) * SA) * 4 +
                                 (kk * 16 + lHi * 8) * 2;
                ldsm_x4(af[mf], saddr);
            }
#pragma unroll
            for (int nb = 0; nb < 2; nb++) {
                int row = wn * 32 + nb * 16 + bNfOff;
                uint32_t saddr = bsBase + (sob + row * SA) * 4 + kk * 32 + bHalf * 16;
                ldsm_x4(bfr[nb], saddr);
            }
#pragma unroll
            for (int mf = 0; mf < 2; mf++)
#pragma unroll
                for (int nf = 0; nf < 4; nf++) {
                    uint32_t b2[2] = { bfr[nf >> 1][(nf & 1) * 2],
                                       bfr[nf >> 1][(nf & 1) * 2 + 1] };
                    mma_f16(acc[mf][nf], af[mf], b2);
                }
        }
        __syncthreads();
    }

    // epilogue -> fp16
#pragma unroll
    for (int mf = 0; mf < 2; mf++)
#pragma unroll
        for (int nf = 0; nf < 4; nf++) {
            int r0 = rowBase + wm * 32 + mf * 16 + g;
            int c  = colBase + wn * 32 + nf * 8 + tig * 2;
            if (r0 < NN)
                *reinterpret_cast<__half2*>(&d_h[(size_t)r0 * DD + c]) =
                    __floats2half2_rn(acc[mf][nf][0], acc[mf][nf][1]);
            int r1 = r0 + 8;
            if (r1 < NN)
                *reinterpret_cast<__half2*>(&d_h[(size_t)r1 * DD + c]) =
                    __floats2half2_rn(acc[mf][nf][2], acc[mf][nf][3]);
        }
}

// ---------------- degree histogram (deg pre-zeroed by previous run) -------
__global__ void hist_kernel(const int* __restrict__ dst0, const int* __restrict__ dst1,
                            const int* __restrict__ dst2) {
    int e = blockIdx.x * blockDim.x + threadIdx.x;
    int r = blockIdx.y;
    if (e >= EE) return;
    const int* dst = (r == 0) ? dst0 : (r == 1) ? dst1 : dst2;
    atomicAdd(&d_deg[r * NN + dst[e]], 1);
}

// ---------------- scan pass 1: block partial sums ----------------
__global__ __launch_bounds__(256) void scan_p1() {
    int b = blockIdx.x, t = threadIdx.x;
    int lane = t & 31, w = t >> 5;
    int base = b * 1024 + t * 4;
    int x = 0;
#pragma unroll
    for (int j = 0; j < 4; j++) {
        int i = base + j;
        if (i < M_TOT) x += d_deg[i];
    }
    x = warp_isum(x);
    __shared__ int ws[8];
    if (lane == 0) ws[w] = x;
    __syncthreads();
    if (t == 0) {
        int tot = 0;
#pragma unroll
        for (int j = 0; j < 8; j++) tot += ws[j];
        d_bsum[b] = tot;
    }
}

// ---------------- scan pass 2 (fused): offsets + deg self-clean ----------
__global__ __launch_bounds__(256) void scan_p23() {
    int b = blockIdx.x, t = threadIdx.x;
    int lane = t & 31, w = t >> 5;
    __shared__ int sb[NB];
    __shared__ int ws[8];

    int vb = (t < NB) ? d_bsum[t] : 0;
    int xb = warp_iscan(vb, lane);
    if (lane == 31) ws[w] = xb;
    __syncthreads();
    if (w == 0) {
        int y = (lane < 8) ? ws[lane] : 0;
        y = warp_iscan(y, lane);
        if (lane < 8) ws[lane] = y;
    }
    __syncthreads();
    int blkb = (w > 0) ? ws[w - 1] : 0;
    if (t < NB) sb[t] = xb + blkb;
    __syncthreads();
    int base_excl = (b > 0) ? sb[b - 1] : 0;
    __syncthreads();

    int base = b * 1024 + t * 4;
    int a[4];
#pragma unroll
    for (int j = 0; j < 4; j++) {
        int i = base + j;
        a[j] = (i < M_TOT) ? d_deg[i] : 0;
    }
    int tot = a[0] + a[1] + a[2] + a[3];
    int x = warp_iscan(tot, lane);
    if (lane == 31) ws[w] = x;
    __syncthreads();
    if (w == 0) {
        int y = (lane < 8) ? ws[lane] : 0;
        y = warp_iscan(y, lane);
        if (lane < 8) ws[lane] = y;
    }
    __syncthreads();
    int blk = (w > 0) ? ws[w - 1] : 0;
    int run = x - tot + blk + base_excl;
#pragma unroll
    for (int j = 0; j < 4; j++) {
        int i = base + j;
        if (i < M_TOT) {
            d_off[i] = run;
            d_cur[i] = run;
            d_deg[i] = 0;
        }
        run += a[j];
    }
    if (b == 0 && t == 0) d_off[M_TOT] = 3 * EE;
}

// ---------------- scatter into CSR ----------------
__global__ void scatter_kernel(const int* __restrict__ src0, const int* __restrict__ dst0,
                               const int* __restrict__ src1, const int* __restrict__ dst1,
                               const int* __restrict__ src2, const int* __restrict__ dst2) {
    int e = blockIdx.x * blockDim.x + threadIdx.x;
    int r = blockIdx.y;
    if (e >= EE) return;
    const int* src = (r == 0) ? src0 : (r == 1) ? src1 : src2;
    const int* dst = (r == 0) ? dst0 : (r == 1) ? dst1 : dst2;
    int dv = dst[e];
    int pos = atomicAdd(&d_cur[r * NN + dv], 1);
    d_ss[pos] = src[e];
}

// ---------------- gather + mean + relu + LN (warp/node, LDG.128, 4-way) ---
__device__ __forceinline__ void accum_row(float (&sm)[8], uint4 x) {
    float2 f0 = __half22float2(*reinterpret_cast<__half2*>(&x.x));
    float2 f1 = __half22float2(*reinterpret_cast<__half2*>(&x.y));
    float2 f2 = __half22float2(*reinterpret_cast<__half2*>(&x.z));
    float2 f3 = __half22float2(*reinterpret_cast<__half2*>(&x.w));
    sm[0] += f0.x; sm[1] += f0.y; sm[2] += f1.x; sm[3] += f1.y;
    sm[4] += f2.x; sm[5] += f2.y; sm[6] += f3.x; sm[7] += f3.y;
}

__global__ __launch_bounds__(256) void agg_ln_kernel(const float* __restrict__ gamma,
                                                     const float* __restrict__ beta,
                                                     float* __restrict__ out) {
    int v = (blockIdx.x * blockDim.x + threadIdx.x) >> 5;
    if (v >= NN) return;
    int lane = threadIdx.x & 31;
    const int co = lane * 8;

    float acc[8];
#pragma unroll
    for (int j = 0; j < 8; j++) acc[j] = 0.0f;

#pragma unroll
    for (int r = 0; r < 3; r++) {
        int s = d_off[r * NN + v];
        int e = d_off[r * NN + v + 1];
        float sm[8];
#pragma unroll
        for (int j = 0; j < 8; j++) sm[j] = 0.0f;

        int i = s;
        for (; i + 4 <= e; i += 4) {
            int u0 = d_ss[i], u1 = d_ss[i + 1], u2 = d_ss[i + 2], u3 = d_ss[i + 3];
            uint4 x0 = *reinterpret_cast<const uint4*>(&d_h[(size_t)u0 * DD + co]);
            uint4 x1 = *reinterpret_cast<const uint4*>(&d_h[(size_t)u1 * DD + co]);
            uint4 x2 = *reinterpret_cast<const uint4*>(&d_h[(size_t)u2 * DD + co]);
            uint4 x3 = *reinterpret_cast<const uint4*>(&d_h[(size_t)u3 * DD + co]);
            accum_row(sm, x0); accum_row(sm, x1); accum_row(sm, x2); accum_row(sm, x3);
        }
        for (; i < e; i++) {
            int u = d_ss[i];
            uint4 x = *reinterpret_cast<const uint4*>(&d_h[(size_t)u * DD + co]);
            accum_row(sm, x);
        }

        float inv = 1.0f / (float)max(e - s, 1);
#pragma unroll
        for (int j = 0; j < 8; j++) acc[j] += sm[j] * inv;
    }

#pragma unroll
    for (int j = 0; j < 8; j++) acc[j] = fmaxf(acc[j] * (1.0f / 3.0f), 0.0f);

    float loc = 0.0f;
#pragma unroll
    for (int j = 0; j < 8; j++) loc += acc[j];
    float mu = warp_sum(loc) * (1.0f / 256.0f);

    float vs = 0.0f;
#pragma unroll
    for (int j = 0; j < 8; j++) {
        float dlt = acc[j] - mu;
        vs += dlt * dlt;
    }
    float var = warp_sum(vs) * (1.0f / 256.0f);
    float rstd = rsqrtf(var + LN_EPS);

    const float4* g4 = reinterpret_cast<const float4*>(gamma);
    const float4* b4 = reinterpret_cast<const float4*>(beta);
    float4 ga = g4[lane * 2], gb = g4[lane * 2 + 1];
    float4 ba = b4[lane * 2], bb = b4[lane * 2 + 1];

    float4 o0, o1;
    o0.x = (acc[0] - mu) * rstd * ga.x + ba.x;
    o0.y = (acc[1] - mu) * rstd * ga.y + ba.y;
    o0.z = (acc[2] - mu) * rstd * ga.z + ba.z;
    o0.w = (acc[3] - mu) * rstd * ga.w + ba.w;
    o1.x = (acc[4] - mu) * rstd * gb.x + bb.x;
    o1.y = (acc[5] - mu) * rstd * gb.y + bb.y;
    o1.z = (acc[6] - mu) * rstd * gb.z + bb.z;
    o1.w = (acc[7] - mu) * rstd * gb.w + bb.w;

    float4* out4 = reinterpret_cast<float4*>(&out[(size_t)v * DD]);
    out4[lane * 2] = o0;
    out4[lane * 2 + 1] = o1;
}

// ---------------- launch ----------------
extern "C" void kernel_launch(void* const* d_in, const int* in_sizes, int n_in,
                              void* d_out, int out_size) {
    const float* feat  = (const float*)d_in[0];
    const float* W0    = (const float*)d_in[1];
    const float* W1    = (const float*)d_in[2];
    const float* W2    = (const float*)d_in[3];
    const float* gamma = (const float*)d_in[7];
    const float* beta  = (const float*)d_in[8];
    const int* src0 = (const int*)d_in[9];
    const int* dst0 = (const int*)d_in[10];
    const int* src1 = (const int*)d_in[11];
    const int* dst1 = (const int*)d_in[12];
    const int* src2 = (const int*)d_in[13];
    const int* dst2 = (const int*)d_in[14];
    float* out = (float*)d_out;

    static cudaStream_t s_side = nullptr;
    static cudaEvent_t ev_fork = nullptr, ev_join = nullptr;
    if (s_side == nullptr) {
        cudaStreamCreateWithFlags(&s_side, cudaStreamNonBlocking);
        cudaEventCreateWithFlags(&ev_fork, cudaEventDisableTiming);
        cudaEventCreateWithFlags(&ev_join, cudaEventDisableTiming);
        cudaFuncSetAttribute(gemm_kernel, cudaFuncAttributeMaxDynamicSharedMemorySize,
                             GEMM_SMEM_BYTES);
    }

    // fork FIRST: side chain has no dependence on prep
    cudaEventRecord(ev_fork, 0);
    cudaStreamWaitEvent(s_side, ev_fork, 0);

    // main: fused prep (Wsum + feat->fp16)                 [idx 0]
    prep_conv_kernel<<<592, 256>>>(feat, W0, W1, W2);

    dim3 egrid((EE + 255) / 256, 3);
    hist_kernel<<<egrid, 256, 0, s_side>>>(dst0, dst1, dst2);   // idx 1
    scan_p1<<<NB, 256, 0, s_side>>>();                          // idx 2

    // main: GEMM                                            [idx 3 - profiled]
    dim3 ggrid((NN + BM - 1) / BM, DD / BN);
    gemm_kernel<<<ggrid, 256, GEMM_SMEM_BYTES, 0>>>();

    scan_p23<<<NB, 256, 0, s_side>>>();                         // idx 4
    scatter_kernel<<<egrid, 256, 0, s_side>>>(src0, dst0, src1, dst1, src2, dst2); // idx 5
    cudaEventRecord(ev_join, s_side);

    cudaStreamWaitEvent(0, ev_join, 0);
    agg_ln_kernel<<<(NN * 32 + 255) / 256, 256>>>(gamma, beta, out);  // idx 6
}